// round 7
// baseline (speedup 1.0000x reference)
#include <cuda_runtime.h>
#include <math_constants.h>

// Exact kNN graph via uniform-grid ring search.
// PyG knn_graph(loop=False): B=16 graphs x n=4096 pts, D=3, k=16.
// Output (float32 flat): [nbr_global | centers | topk_d2], each total_n*K,
// ordering (b*n+i)*K + m (matches reference reshape(-1)).
//
// Kernel 1 (build): per-graph counting sort of points into G^3 cells.
// Kernel 2 (query): per point, expand Chebyshev rings of cells, maintaining
// a sorted K+1 list of packed u64 keys (monotone dist bits << 32 | orig idx),
// which reproduces jax.lax.top_k's (value, lower-index) ordering exactly.
// Stop bound: after finishing ring r, any unexamined point is >= r*h away
// (holds under coordinate clamping: clamped outliers lie strictly outward of
// their assigned edge cell, so per-axis gaps only grow).

#define K     16
#define KP1   17
#define NPER  4096
#define TPB   256
#define CPG   (NPER / TPB)   // 16 CTAs per graph
#define NG    16             // graphs (fixed by the problem)
#define G     20             // cells per axis
#define GC    (G * G * G)    // 8000
#define GCP   8192           // padded for the block scan (256*32)
#define LO    (-4.5f)
#define HCELL 0.45f

__device__ float4 g_sorted[NG][NPER];  // (x, y, z, bitcast orig local idx)
__device__ int2   g_range [NG][GC];    // per cell: [start, end) in sorted order

__device__ __forceinline__ int cellCoord(float v) {
    int c = (int)floorf((v - LO) * (1.0f / HCELL));
    return min(G - 1, max(0, c));
}

// ---------------------------------------------------------------- build ----
__global__ __launch_bounds__(TPB, 1)
void knn_build_kernel(const float* __restrict__ pos)
{
    __shared__ int cnt[GCP];
    __shared__ int partial[TPB];
    const int g = blockIdx.x, tid = threadIdx.x, base = g * NPER;
    const float* gp = pos + (size_t)base * 3;

    for (int i = tid; i < GCP; i += TPB) cnt[i] = 0;
    __syncthreads();

    // histogram
    for (int p = tid; p < NPER; p += TPB) {
        const float x = gp[3 * p], y = gp[3 * p + 1], z = gp[3 * p + 2];
        const int id = (cellCoord(z) * G + cellCoord(y)) * G + cellCoord(x);
        atomicAdd(&cnt[id], 1);
    }
    __syncthreads();

    // exclusive scan over GCP (32 cells per thread)
    const int c0 = tid * 32;
    int s = 0;
    for (int i = 0; i < 32; ++i) s += cnt[c0 + i];
    partial[tid] = s;
    __syncthreads();
    if (tid == 0) {
        int run = 0;
        for (int t = 0; t < TPB; ++t) { const int v = partial[t]; partial[t] = run; run += v; }
    }
    __syncthreads();
    int run = partial[tid];
    for (int i = 0; i < 32; ++i) { const int v = cnt[c0 + i]; cnt[c0 + i] = run; run += v; }
    __syncthreads();

    // publish [start, end) per cell BEFORE the scatter mutates the cursors
    for (int i = tid; i < GC; i += TPB)
        g_range[g][i] = make_int2(cnt[i], cnt[i + 1]);
    __syncthreads();

    // scatter points into cell-sorted order
    for (int p = tid; p < NPER; p += TPB) {
        const float x = gp[3 * p], y = gp[3 * p + 1], z = gp[3 * p + 2];
        const int id = (cellCoord(z) * G + cellCoord(y)) * G + cellCoord(x);
        const int slot = atomicAdd(&cnt[id], 1);
        g_sorted[g][slot] = make_float4(x, y, z, __int_as_float(p));
    }
}

// ---------------------------------------------------------------- query ----
__device__ __forceinline__ void insert17(unsigned long long kk,
                                         unsigned long long (&bk)[KP1])
{
#pragma unroll
    for (int m = 0; m < KP1; ++m) {
        const bool sw = kk < bk[m];              // strict: ties keep lower key
        const unsigned long long lo2 = sw ? kk : bk[m];
        kk    = sw ? bk[m] : kk;
        bk[m] = lo2;
    }
}

__global__ __launch_bounds__(TPB, 2)
void knn_query_kernel(float* __restrict__ out, int total_n)
{
    extern __shared__ float smem[];
    float4* pts = (float4*)smem;           // [NPER] sorted points (64 KB)
    float*  ssm = smem + 4 * NPER;         // [NPER] squared norms  (16 KB)

    const int graph = blockIdx.x / CPG;
    const int base  = graph * NPER;
    const int tid   = threadIdx.x;

    // Stage sorted points + norms. Norm op order matches the dot chain so
    // the self-distance is exactly +0.
    for (int p = tid; p < NPER; p += TPB) {
        const float4 v = g_sorted[graph][p];
        pts[p] = v;
        ssm[p] = fmaf(v.z, v.z, fmaf(v.y, v.y, v.x * v.x));
    }
    __syncthreads();

    const int    s  = (blockIdx.x % CPG) * TPB + tid;   // sorted slot
    const float4 Q  = pts[s];
    const float  qx = Q.x, qy = Q.y, qz = Q.z;
    const float  qs = ssm[s];
    const int    qi = __float_as_int(Q.w);              // original local idx
    const int    qcx = cellCoord(qx), qcy = cellCoord(qy), qcz = cellCoord(qz);

    unsigned long long bk[KP1];
#pragma unroll
    for (int m = 0; m < KP1; ++m) bk[m] = ~0ull;

    const int2* __restrict__ rng = g_range[graph];

    // d = (qs + s_j) - 2*dot: identical op order/rounding to the reference
    // formula. Key = (monotone(d bits) << 32) | orig_idx — exact
    // (value, lower-index) lexicographic order of jax.lax.top_k.
#define PROC_CELL(cid)                                                         \
    do {                                                                       \
        const int2 rg_ = rng[(cid)];                                           \
        for (int p_ = rg_.x; p_ < rg_.y; ++p_) {                               \
            const float4 P_ = pts[p_];                                         \
            const float dot_ = fmaf(qz, P_.z, fmaf(qy, P_.y, qx * P_.x));      \
            const float d_   = fmaf(-2.f, dot_, qs + ssm[p_]);                 \
            unsigned ub_ = __float_as_uint(d_);                                \
            ub_ ^= ((unsigned)(((int)ub_) >> 31)) | 0x80000000u;               \
            const unsigned long long key_ =                                    \
                ((unsigned long long)ub_ << 32) | __float_as_uint(P_.w);       \
            if (key_ < bk[KP1 - 1]) insert17(key_, bk);                        \
        }                                                                      \
    } while (0)

    for (int r = 0; ; ++r) {
        if (r == 0) {
            PROC_CELL((qcz * G + qcy) * G + qcx);
        } else {
            for (int dz = -r; dz <= r; ++dz) {
                const int cz = qcz + dz;
                if ((unsigned)cz >= G) continue;
                const bool zf = (dz == -r) | (dz == r);
                for (int dy = -r; dy <= r; ++dy) {
                    const int cy = qcy + dy;
                    if ((unsigned)cy >= G) continue;
                    const bool face = zf | (dy == -r) | (dy == r);
                    const int  step = face ? 1 : (2 * r);
                    const int  rowb = (cz * G + cy) * G;
                    for (int dx = -r; dx <= r; dx += step) {
                        const int cx = qcx + dx;
                        if ((unsigned)cx >= G) continue;
                        PROC_CELL(rowb + cx);
                    }
                }
            }
        }
        // Stop: list full and worst <= (r*h)^2 (0.998 safety for FP rounding;
        // conservative direction — at worst one extra ring).
        if (bk[KP1 - 1] != ~0ull) {
            const unsigned hi = (unsigned)(bk[KP1 - 1] >> 32);
            const unsigned wu = (hi & 0x80000000u) ? (hi ^ 0x80000000u) : ~hi;
            const float worst = __uint_as_float(wu);
            const float bound = (float)r * HCELL;
            if (worst <= 0.998f * bound * bound) break;
        }
        if (r >= G) break;   // entire grid covered
    }
#undef PROC_CELL

    // Emit: drop the single self entry (idx == qi, d == +0), keep first K.
    const int    gq = base + qi;
    const size_t Nk = (size_t)total_n * K;
    int w = 0;
#pragma unroll
    for (int m = 0; m < KP1; ++m) {
        const int      idx = (int)(unsigned)bk[m];
        const unsigned hi  = (unsigned)(bk[m] >> 32);
        const unsigned du  = (hi & 0x80000000u) ? (hi ^ 0x80000000u) : ~hi;
        if (idx != qi && w < K) {
            const size_t e = (size_t)gq * K + w;
            out[e]          = (float)(idx + base);
            out[Nk + e]     = (float)gq;
            out[2 * Nk + e] = __uint_as_float(du);
            ++w;
        }
    }
}

extern "C" void kernel_launch(void* const* d_in, const int* in_sizes, int n_in,
                              void* d_out, int out_size)
{
    const float* pos = (const float*)d_in[0];
    const int total_n = in_sizes[0] / 3;
    const int ngraphs = total_n / NPER;

    knn_build_kernel<<<ngraphs, TPB>>>(pos);

    const int smem_bytes = (4 * NPER) * (int)sizeof(float4) / 4
                         + NPER * (int)sizeof(float);           // 80 KB
    cudaFuncSetAttribute(knn_query_kernel,
                         cudaFuncAttributeMaxDynamicSharedMemorySize, smem_bytes);
    knn_query_kernel<<<ngraphs * CPG, TPB, smem_bytes>>>((float*)d_out, total_n);
}